// round 15
// baseline (speedup 1.0000x reference)
#include <cuda_runtime.h>
#include <cuda_fp16.h>

// Fixed shapes.
#define Bv 2
#define Cv 3
#define Dv 128
#define Hv 192
#define Wv 192
#define HW (Hv * Wv)

// Coefficient scratch in global (keeps smem = tile only -> occupancy 3).
// Layout: [0:192) cxs (cx shifted), [192:384) 1/ax, [384:576) bx/ax
__device__ __align__(16) float g_xc[576];
__device__ __align__(16) float g_yc[576];   // same layout for y

// ---------------------------------------------------------------------------
// Kernel 1: fused x-solve (W) + y-solve (H), one CTA per (b,c,d) slice.
// Tile: 192x192 fp16 = 73728B exactly, rotation-swizzled (half j of row k at
// (j + 8k) mod 192): conflict-free 16B row sweeps AND scalar column sweeps,
// no padding -> 3 CTAs/SM. All math fp32.
// ---------------------------------------------------------------------------
__global__ __launch_bounds__(192, 3)
void xy_solve_kernel(const float* __restrict__ in, float* __restrict__ out,
                     const float* __restrict__ ax, const float* __restrict__ bx,
                     const float* __restrict__ cx,
                     const float* __restrict__ ay, const float* __restrict__ by,
                     const float* __restrict__ cy)
{
    extern __shared__ __align__(16) __half tile[];   // 192*192 halves

    const int t = threadIdx.x;

    // ---- coefficients -> global scratch (every CTA writes identical values;
    // __syncthreads orders our own writes before our reads) ------------------
    {
        float a = ax[t];
        g_xc[t]       = (t >= 1)      ? cx[t - 1] : 0.0f;
        g_xc[192 + t] = 1.0f / a;
        g_xc[384 + t] = (t < Wv - 1)  ? bx[t] / a : 0.0f;
        float ya = ay[t];
        g_yc[t]       = (t >= 1)      ? cy[t - 1] : 0.0f;
        g_yc[192 + t] = 1.0f / ya;
        g_yc[384 + t] = (t < Hv - 1)  ? by[t] / ya : 0.0f;
    }

    // ---- fill: fp32 float4 -> fp16x4 at swizzled positions ------------------
    {
        const float4* g4 = (const float4*)(in + (size_t)blockIdx.x * HW);
        const int c4 = t % 48;            // float4 column 0..47
        const int r0 = t / 48;            // row-within-group 0..3
        #pragma unroll
        for (int it = 0; it < 48; it++) {
            const int k = it * 4 + r0;
            float4 v = g4[k * 48 + c4];
            const int jp = (4 * c4 + 8 * k) % 192;   // swizzled half-position
            __half2* dst = (__half2*)(tile + k * 192 + jp);
            dst[0] = __floats2half2_rn(v.x, v.y);
            dst[1] = __floats2half2_rn(v.z, v.w);
        }
    }
    __syncthreads();

    const float* cxs = g_xc;
    const float* iax = g_xc + 192;
    const float* fx  = g_xc + 384;
    const float* cys = g_yc;
    const float* iay = g_yc + 192;
    const float* fy  = g_yc + 384;

    // ---- x-solve: thread t owns row h = t -----------------------------------
    {
        __half* row = tile + t * 192;
        int p = (8 * t) % 192;            // swizzled position of group m=0

        // forward, group 0 (j = 0..7)
        float carry;
        {
            uint4 raw = *(const uint4*)(row + p);
            __half2* hp = (__half2*)&raw;
            float2 e0 = __half22float2(hp[0]);
            float2 e1 = __half22float2(hp[1]);
            float2 e2 = __half22float2(hp[2]);
            float2 e3 = __half22float2(hp[3]);
            carry = e0.x;
            e0.y = fmaf(-cxs[1], carry, e0.y);
            e1.x = fmaf(-cxs[2], e0.y,  e1.x);
            e1.y = fmaf(-cxs[3], e1.x,  e1.y);
            e2.x = fmaf(-cxs[4], e1.y,  e2.x);
            e2.y = fmaf(-cxs[5], e2.x,  e2.y);
            e3.x = fmaf(-cxs[6], e2.y,  e3.x);
            e3.y = fmaf(-cxs[7], e3.x,  e3.y);
            carry = e3.y;
            hp[0] = __floats2half2_rn(e0.x, e0.y);
            hp[1] = __floats2half2_rn(e1.x, e1.y);
            hp[2] = __floats2half2_rn(e2.x, e2.y);
            hp[3] = __floats2half2_rn(e3.x, e3.y);
            *(uint4*)(row + p) = raw;
        }
        // forward, groups 1..23
        #pragma unroll
        for (int m = 1; m < 24; m++) {
            p += 8; if (p >= 192) p -= 192;
            const int g = 8 * m;
            uint4 raw = *(const uint4*)(row + p);
            __half2* hp = (__half2*)&raw;
            float4 c0 = *(const float4*)(cxs + g);
            float4 c1 = *(const float4*)(cxs + g + 4);
            float2 e0 = __half22float2(hp[0]);
            float2 e1 = __half22float2(hp[1]);
            float2 e2 = __half22float2(hp[2]);
            float2 e3 = __half22float2(hp[3]);
            e0.x = fmaf(-c0.x, carry, e0.x);
            e0.y = fmaf(-c0.y, e0.x,  e0.y);
            e1.x = fmaf(-c0.z, e0.y,  e1.x);
            e1.y = fmaf(-c0.w, e1.x,  e1.y);
            e2.x = fmaf(-c1.x, e1.y,  e2.x);
            e2.y = fmaf(-c1.y, e2.x,  e2.y);
            e3.x = fmaf(-c1.z, e2.y,  e3.x);
            e3.y = fmaf(-c1.w, e3.x,  e3.y);
            carry = e3.y;
            hp[0] = __floats2half2_rn(e0.x, e0.y);
            hp[1] = __floats2half2_rn(e1.x, e1.y);
            hp[2] = __floats2half2_rn(e2.x, e2.y);
            hp[3] = __floats2half2_rn(e3.x, e3.y);
            *(uint4*)(row + p) = raw;
        }

        // backward, group 23 (j = 184..191), p currently at m=23
        {
            const int g = 184;
            uint4 raw = *(const uint4*)(row + p);
            __half2* hp = (__half2*)&raw;
            float4 f1 = *(const float4*)(fx + g + 4);
            float4 f0 = *(const float4*)(fx + g);
            float4 i1 = *(const float4*)(iax + g + 4);
            float4 i0 = *(const float4*)(iax + g);
            float2 e0 = __half22float2(hp[0]);
            float2 e1 = __half22float2(hp[1]);
            float2 e2 = __half22float2(hp[2]);
            float2 e3 = __half22float2(hp[3]);
            e3.y = carry * i1.w;                         // z_{191}
            e3.x = fmaf(-f1.z, e3.y, e3.x * i1.z);
            e2.y = fmaf(-f1.y, e3.x, e2.y * i1.y);
            e2.x = fmaf(-f1.x, e2.y, e2.x * i1.x);
            e1.y = fmaf(-f0.w, e2.x, e1.y * i0.w);
            e1.x = fmaf(-f0.z, e1.y, e1.x * i0.z);
            e0.y = fmaf(-f0.y, e1.x, e0.y * i0.y);
            e0.x = fmaf(-f0.x, e0.y, e0.x * i0.x);
            carry = e0.x;
            hp[0] = __floats2half2_rn(e0.x, e0.y);
            hp[1] = __floats2half2_rn(e1.x, e1.y);
            hp[2] = __floats2half2_rn(e2.x, e2.y);
            hp[3] = __floats2half2_rn(e3.x, e3.y);
            *(uint4*)(row + p) = raw;
        }
        // backward, groups 22..0
        #pragma unroll
        for (int m = 22; m >= 0; m--) {
            p -= 8; if (p < 0) p += 192;
            const int g = 8 * m;
            uint4 raw = *(const uint4*)(row + p);
            __half2* hp = (__half2*)&raw;
            float4 f0 = *(const float4*)(fx + g);
            float4 f1 = *(const float4*)(fx + g + 4);
            float4 i0 = *(const float4*)(iax + g);
            float4 i1 = *(const float4*)(iax + g + 4);
            float2 e0 = __half22float2(hp[0]);
            float2 e1 = __half22float2(hp[1]);
            float2 e2 = __half22float2(hp[2]);
            float2 e3 = __half22float2(hp[3]);
            e3.y = fmaf(-f1.w, carry, e3.y * i1.w);
            e3.x = fmaf(-f1.z, e3.y,  e3.x * i1.z);
            e2.y = fmaf(-f1.y, e3.x,  e2.y * i1.y);
            e2.x = fmaf(-f1.x, e2.y,  e2.x * i1.x);
            e1.y = fmaf(-f0.w, e2.x,  e1.y * i0.w);
            e1.x = fmaf(-f0.z, e1.y,  e1.x * i0.z);
            e0.y = fmaf(-f0.y, e1.x,  e0.y * i0.y);
            e0.x = fmaf(-f0.x, e0.y,  e0.x * i0.x);
            carry = e0.x;
            hp[0] = __floats2half2_rn(e0.x, e0.y);
            hp[1] = __floats2half2_rn(e1.x, e1.y);
            hp[2] = __floats2half2_rn(e2.x, e2.y);
            hp[3] = __floats2half2_rn(e3.x, e3.y);
            *(uint4*)(row + p) = raw;
        }
    }
    __syncthreads();

    // ---- y-solve: thread t owns column w = t; bwd streams fp32 to gmem ------
    {
        int p = t;                                  // swizzled pos at k=0
        float carry = __half2float(tile[p]);
        #pragma unroll 8
        for (int k = 1; k < Hv; k++) {
            p += 8; if (p >= 192) p -= 192;
            const int a = k * 192 + p;
            carry = fmaf(-cys[k], carry, __half2float(tile[a]));
            tile[a] = __float2half_rn(carry);
        }
        float* o = out + (size_t)blockIdx.x * HW;
        carry = carry * iay[Hv - 1];
        o[(Hv - 1) * Wv + t] = carry;
        #pragma unroll 8
        for (int k = Hv - 2; k >= 0; k--) {
            p -= 8; if (p < 0) p += 192;
            carry = fmaf(-fy[k], carry,
                         __half2float(tile[k * 192 + p]) * iay[k]);
            o[k * Wv + t] = carry;
        }
    }
}

// ---------------------------------------------------------------------------
// Kernel 2: z-solve (D), in-place. Register-resident column per thread.
// (Unchanged since R5 — protected.)
// ---------------------------------------------------------------------------
__global__ __launch_bounds__(192, 2)
void z_solve_kernel(float* __restrict__ io,
                    const float* __restrict__ az, const float* __restrict__ bz,
                    const float* __restrict__ cz)
{
    __shared__ float s_c[Dv - 1];
    __shared__ float s_ia[Dv];
    __shared__ float s_f[Dv - 1];

    const int t = threadIdx.x;
    if (t < Dv)     { s_ia[t] = 1.0f / az[t]; }
    if (t < Dv - 1) { s_c[t] = cz[t]; s_f[t] = bz[t] / az[t]; }
    __syncthreads();

    const int n  = blockIdx.x;            // over B*C*H
    const int h  = n % Hv;
    const int bc = n / Hv;
    float* g = io + (size_t)bc * (Dv * HW) + (size_t)h * Wv + t;

    float y[Dv];
    #pragma unroll
    for (int d = 0; d < Dv; d++)
        y[d] = g[(size_t)d * HW];

    #pragma unroll
    for (int d = 1; d < Dv; d++)
        y[d] = fmaf(-s_c[d - 1], y[d - 1], y[d]);

    float carry = y[Dv - 1] * s_ia[Dv - 1];
    g[(size_t)(Dv - 1) * HW] = carry;
    #pragma unroll
    for (int d = Dv - 2; d >= 0; d--) {
        carry = fmaf(-s_f[d], carry, y[d] * s_ia[d]);
        g[(size_t)d * HW] = carry;
    }
}

// ---------------------------------------------------------------------------
extern "C" void kernel_launch(void* const* d_in, const int* in_sizes, int n_in,
                              void* d_out, int out_size)
{
    const float* field = (const float*)d_in[0];
    const float* ax = (const float*)d_in[1];
    const float* bx = (const float*)d_in[2];
    const float* cx = (const float*)d_in[3];
    const float* ay = (const float*)d_in[4];
    const float* by = (const float*)d_in[5];
    const float* cy = (const float*)d_in[6];
    const float* az = (const float*)d_in[7];
    const float* bz = (const float*)d_in[8];
    const float* cz = (const float*)d_in[9];
    float* out = (float*)d_out;

    const int smem_xy = Hv * Wv * 2;   // 73728 B exactly (72 KiB)

    cudaFuncSetAttribute(xy_solve_kernel,
                         cudaFuncAttributeMaxDynamicSharedMemorySize, smem_xy);

    xy_solve_kernel<<<Bv * Cv * Dv, 192, smem_xy>>>(field, out,
                                                    ax, bx, cx, ay, by, cy);
    z_solve_kernel<<<Bv * Cv * Hv, 192>>>(out, az, bz, cz);
}

// round 17
// speedup vs baseline: 1.3254x; 1.3254x over previous
#include <cuda_runtime.h>
#include <cuda_fp16.h>

// Fixed shapes.
#define Bv 2
#define Cv 3
#define Dv 128
#define Hv 192
#define Wv 192
#define HW (Hv * Wv)
#define SP 200             // fp16 tile row stride in halves: 100 words == 4 (mod 32)
                           // -> conflict-free 16B row sweeps AND column access

// fp16 intermediate between xy and z (sanctioned __device__ scratch).
__device__ __half g_mid[(size_t)Bv * Cv * Dv * Hv * Wv];   // 56.6 MB

// ---------------------------------------------------------------------------
// Kernel 1: fused x-solve (W) + y-solve (H), one CTA per (b,c,d) slice.
// Tile fp16 in smem (76.8KB) -> occupancy 2; all math fp32.  (R10 structure,
// proven 71us; only change: y-backward streams fp16 to g_mid.)
// ---------------------------------------------------------------------------
__global__ __launch_bounds__(192, 2)
void xy_solve_kernel(const float* __restrict__ in,
                     const float* __restrict__ ax, const float* __restrict__ bx,
                     const float* __restrict__ cx,
                     const float* __restrict__ ay, const float* __restrict__ by,
                     const float* __restrict__ cy)
{
    extern __shared__ __align__(16) unsigned char smraw[];
    __half* tile = (__half*)smraw;                       // Hv * SP halves
    float*  fco  = (float*)(smraw + Hv * SP * 2);        // 6 * 192 floats
    float* s_cxs = fco;            // [i] = cx[i-1], [0] unused
    float* s_iax = fco + 192;      // 1/ax
    float* s_fx  = fco + 384;      // bx/ax, [191] unused
    float* s_cys = fco + 576;      // cy shifted
    float* s_iay = fco + 768;      // 1/ay
    float* s_fy  = fco + 960;      // by/ay, [191] unused

    const int t = threadIdx.x;

    if (t < Wv) {
        float a = ax[t];
        s_iax[t] = 1.0f / a;
        s_cxs[t] = (t >= 1)     ? cx[t - 1] : 0.0f;
        s_fx[t]  = (t < Wv - 1) ? bx[t] / a : 0.0f;
    }
    if (t < Hv) {
        float a = ay[t];
        s_iay[t] = 1.0f / a;
        s_cys[t] = (t >= 1)     ? cy[t - 1] : 0.0f;
        s_fy[t]  = (t < Hv - 1) ? by[t] / a : 0.0f;
    }

    // ---- load: fp32 float4 from gmem -> fp16x4 into tile (deep MLP) --------
    {
        const float4* g4 = (const float4*)(in + (size_t)blockIdx.x * HW);
        const int c4 = t % 48;            // float4 column 0..47
        const int r0 = t / 48;            // row-within-group 0..3
        #pragma unroll
        for (int it = 0; it < 48; it++) {
            const int k = it * 4 + r0;    // row
            float4 v = g4[k * 48 + c4];
            __half2 h01 = __floats2half2_rn(v.x, v.y);
            __half2 h23 = __floats2half2_rn(v.z, v.w);
            *(__half2*)(tile + k * SP + c4 * 4)     = h01;
            *(__half2*)(tile + k * SP + c4 * 4 + 2) = h23;
        }
    }
    __syncthreads();

    // ---- x-solve: thread t owns row h = t -----------------------------------
    {
        __half* row = tile + t * SP;
        float carry = __half2float(row[0]);
        #pragma unroll
        for (int i = 1; i < 8; i++) {
            carry = fmaf(-s_cxs[i], carry, __half2float(row[i]));
            row[i] = __float2half_rn(carry);
        }
        #pragma unroll 2
        for (int g = 8; g < Wv; g += 8) {
            uint4 raw = *(const uint4*)(row + g);            // 8 halves, 16B
            __half2* hp = (__half2*)&raw;
            float2 p0 = __half22float2(hp[0]);
            float2 p1 = __half22float2(hp[1]);
            float2 p2 = __half22float2(hp[2]);
            float2 p3 = __half22float2(hp[3]);
            p0.x = fmaf(-s_cxs[g + 0], carry, p0.x);
            p0.y = fmaf(-s_cxs[g + 1], p0.x,  p0.y);
            p1.x = fmaf(-s_cxs[g + 2], p0.y,  p1.x);
            p1.y = fmaf(-s_cxs[g + 3], p1.x,  p1.y);
            p2.x = fmaf(-s_cxs[g + 4], p1.y,  p2.x);
            p2.y = fmaf(-s_cxs[g + 5], p2.x,  p2.y);
            p3.x = fmaf(-s_cxs[g + 6], p2.y,  p3.x);
            p3.y = fmaf(-s_cxs[g + 7], p3.x,  p3.y);
            carry = p3.y;
            hp[0] = __floats2half2_rn(p0.x, p0.y);
            hp[1] = __floats2half2_rn(p1.x, p1.y);
            hp[2] = __floats2half2_rn(p2.x, p2.y);
            hp[3] = __floats2half2_rn(p3.x, p3.y);
            *(uint4*)(row + g) = raw;
        }
        carry = carry * s_iax[Wv - 1];
        row[Wv - 1] = __float2half_rn(carry);
        #pragma unroll
        for (int i = Wv - 2; i >= Wv - 8; i--) {
            carry = fmaf(-s_fx[i], carry, __half2float(row[i]) * s_iax[i]);
            row[i] = __float2half_rn(carry);
        }
        #pragma unroll 2
        for (int g = Wv - 16; g >= 0; g -= 8) {
            uint4 raw = *(const uint4*)(row + g);
            __half2* hp = (__half2*)&raw;
            float2 p0 = __half22float2(hp[0]);
            float2 p1 = __half22float2(hp[1]);
            float2 p2 = __half22float2(hp[2]);
            float2 p3 = __half22float2(hp[3]);
            p3.y = fmaf(-s_fx[g + 7], carry, p3.y * s_iax[g + 7]);
            p3.x = fmaf(-s_fx[g + 6], p3.y,  p3.x * s_iax[g + 6]);
            p2.y = fmaf(-s_fx[g + 5], p3.x,  p2.y * s_iax[g + 5]);
            p2.x = fmaf(-s_fx[g + 4], p2.y,  p2.x * s_iax[g + 4]);
            p1.y = fmaf(-s_fx[g + 3], p2.x,  p1.y * s_iax[g + 3]);
            p1.x = fmaf(-s_fx[g + 2], p1.y,  p1.x * s_iax[g + 2]);
            p0.y = fmaf(-s_fx[g + 1], p1.x,  p0.y * s_iax[g + 1]);
            p0.x = fmaf(-s_fx[g + 0], p0.y,  p0.x * s_iax[g + 0]);
            carry = p0.x;
            hp[0] = __floats2half2_rn(p0.x, p0.y);
            hp[1] = __floats2half2_rn(p1.x, p1.y);
            hp[2] = __floats2half2_rn(p2.x, p2.y);
            hp[3] = __floats2half2_rn(p3.x, p3.y);
            *(uint4*)(row + g) = raw;
        }
    }
    __syncthreads();

    // ---- y-solve: thread t owns column w = t; bwd streams FP16 to g_mid -----
    {
        float carry = __half2float(tile[t]);
        #pragma unroll 8
        for (int i = 1; i < Hv; i++) {
            carry = fmaf(-s_cys[i], carry, __half2float(tile[i * SP + t]));
            tile[i * SP + t] = __float2half_rn(carry);
        }
        __half* o = g_mid + (size_t)blockIdx.x * HW;
        carry = carry * s_iay[Hv - 1];
        o[(Hv - 1) * Wv + t] = __float2half_rn(carry);
        #pragma unroll 8
        for (int i = Hv - 2; i >= 0; i--) {
            carry = fmaf(-s_fy[i], carry,
                         __half2float(tile[i * SP + t]) * s_iay[i]);
            o[i * Wv + t] = __float2half_rn(carry);
        }
    }
}

// ---------------------------------------------------------------------------
// Kernel 2: z-solve (D). Reads fp16 g_mid, writes fp32 out. Register-resident
// column per thread (R5 structure, proven).
// ---------------------------------------------------------------------------
__global__ __launch_bounds__(192, 2)
void z_solve_kernel(float* __restrict__ out,
                    const float* __restrict__ az, const float* __restrict__ bz,
                    const float* __restrict__ cz)
{
    __shared__ float s_c[Dv - 1];
    __shared__ float s_ia[Dv];
    __shared__ float s_f[Dv - 1];

    const int t = threadIdx.x;
    if (t < Dv)     { s_ia[t] = 1.0f / az[t]; }
    if (t < Dv - 1) { s_c[t] = cz[t]; s_f[t] = bz[t] / az[t]; }
    __syncthreads();

    const int n  = blockIdx.x;            // over B*C*H
    const int h  = n % Hv;
    const int bc = n / Hv;
    const size_t base = (size_t)bc * (Dv * HW) + (size_t)h * Wv + t;
    const __half* gi = g_mid + base;
    float*        go = out   + base;

    // Load entire fp16 column into fp32 registers (deep MLP, coalesced).
    float y[Dv];
    #pragma unroll
    for (int d = 0; d < Dv; d++)
        y[d] = __half2float(gi[(size_t)d * HW]);

    #pragma unroll
    for (int d = 1; d < Dv; d++)
        y[d] = fmaf(-s_c[d - 1], y[d - 1], y[d]);

    float carry = y[Dv - 1] * s_ia[Dv - 1];
    go[(size_t)(Dv - 1) * HW] = carry;
    #pragma unroll
    for (int d = Dv - 2; d >= 0; d--) {
        carry = fmaf(-s_f[d], carry, y[d] * s_ia[d]);
        go[(size_t)d * HW] = carry;
    }
}

// ---------------------------------------------------------------------------
extern "C" void kernel_launch(void* const* d_in, const int* in_sizes, int n_in,
                              void* d_out, int out_size)
{
    const float* field = (const float*)d_in[0];
    const float* ax = (const float*)d_in[1];
    const float* bx = (const float*)d_in[2];
    const float* cx = (const float*)d_in[3];
    const float* ay = (const float*)d_in[4];
    const float* by = (const float*)d_in[5];
    const float* cy = (const float*)d_in[6];
    const float* az = (const float*)d_in[7];
    const float* bz = (const float*)d_in[8];
    const float* cz = (const float*)d_in[9];
    float* out = (float*)d_out;

    const int smem_xy = Hv * SP * 2 + 6 * 192 * (int)sizeof(float);  // ~81.4KB

    cudaFuncSetAttribute(xy_solve_kernel,
                         cudaFuncAttributeMaxDynamicSharedMemorySize, smem_xy);

    xy_solve_kernel<<<Bv * Cv * Dv, 192, smem_xy>>>(field,
                                                    ax, bx, cx, ay, by, cy);
    z_solve_kernel<<<Bv * Cv * Hv, 192>>>(out, az, bz, cz);
}